// round 1
// baseline (speedup 1.0000x reference)
#include <cuda_runtime.h>
#include <cuda_bf16.h>

// ISTFT: B=8192 batch, F=257 bins, T=6 frames, n_fft=512, hop=128, out len 600.
// One CTA per batch element. irfft-512 done as 256-pt complex IFFT via the
// real-FFT half-size decomposition. Fully fused: load -> irfft -> window ->
// overlap-add -> COLA envelope division -> crop.

#define NTHREADS 256

__global__ __launch_bounds__(NTHREADS) void istft_kernel(
    const float* __restrict__ x,   // [B, 1, 257, 6, 2] contiguous
    float* __restrict__ out)       // [B, 1, 600]
{
    const int b   = blockIdx.x;
    const int tid = threadIdx.x;

    __shared__ float  raw[3084];        // one batch element's input (contiguous)
    __shared__ float2 Z[6][256];        // per-frame complex work buffer

    // ---- 1. coalesced staging: 3084 floats = 771 float4 ----
    {
        const float4* src = reinterpret_cast<const float4*>(x + (size_t)b * 3084);
        float4* dst = reinterpret_cast<float4*>(raw);
        #pragma unroll
        for (int i = tid; i < 771; i += NTHREADS) dst[i] = src[i];
    }
    __syncthreads();

    // ---- 2. build Z[k] = E[k] + i*O[k], written bit-reversed ----
    // E[k] = (X[k] + conj(X[256-k]))/2
    // O[k] = (X[k] - conj(X[256-k]))/2 * e^{+2*pi*i*k/512}
    // DC/Nyquist imaginary parts are ignored (irfft semantics).
    #pragma unroll
    for (int item = tid; item < 6 * 256; item += NTHREADS) {
        const int k = item & 255;
        const int t = item >> 8;
        float Xr = raw[k * 12 + t * 2 + 0];
        float Xi = raw[k * 12 + t * 2 + 1];
        const int m = 256 - k;                  // k=0 -> Nyquist bin 256
        float Yr = raw[m * 12 + t * 2 + 0];
        float Yi = raw[m * 12 + t * 2 + 1];
        if (k == 0) { Xi = 0.0f; Yi = 0.0f; }   // drop DC & Nyquist imag

        const float Er = 0.5f * (Xr + Yr);
        const float Ei = 0.5f * (Xi - Yi);
        const float Dr = 0.5f * (Xr - Yr);
        const float Di = 0.5f * (Xi + Yi);

        float s, c;                              // e^{+2*pi*i*k/512} = e^{i*pi*k/256}
        sincospif((float)k * (1.0f / 256.0f), &s, &c);
        const float Or = Dr * c - Di * s;
        const float Oi = Dr * s + Di * c;

        const int kr = __brev((unsigned)k) >> 24;   // 8-bit reversal
        Z[t][kr] = make_float2(Er - Oi, Ei + Or);
    }
    __syncthreads();

    // ---- 3. in-place radix-2 DIT inverse FFT (256 pts x 6 frames) ----
    #pragma unroll
    for (int stage = 1; stage <= 8; stage++) {
        const int len  = 1 << stage;
        const int half = len >> 1;
        #pragma unroll
        for (int item = tid; item < 6 * 128; item += NTHREADS) {
            const int bfly  = item & 127;
            const int t     = item >> 7;
            const int pos   = bfly & (half - 1);
            const int group = bfly >> (stage - 1);
            const int i0    = group * len + pos;
            const int i1    = i0 + half;

            float s, c;                          // e^{+2*pi*i*pos/len}
            sincospif((float)pos * (2.0f / (float)len), &s, &c);

            const float2 u = Z[t][i0];
            const float2 v = Z[t][i1];
            const float vr = v.x * c - v.y * s;
            const float vi = v.x * s + v.y * c;
            Z[t][i0] = make_float2(u.x + vr, u.y + vi);
            Z[t][i1] = make_float2(u.x - vr, u.y - vi);
        }
        __syncthreads();
    }
    // now z[j] = Z[t][j] holds frame samples: frame[2j]=Re z[j], frame[2j+1]=Im z[j]
    // (unnormalized by 1/256; folded into the final scale below)

    // ---- 4. window + overlap-add + COLA envelope + crop ----
    for (int n = tid; n < 600; n += NTHREADS) {
        const int p = n + 256;                  // center=True trim of n_fft/2
        float acc = 0.0f;
        float env = 0.0f;
        #pragma unroll
        for (int t = 0; t < 6; t++) {
            const int j = p - 128 * t;
            if (j >= 0 && j < 512) {
                // hann periodic: 0.5 - 0.5*cos(2*pi*j/512) = 0.5 - 0.5*cos(pi*j/256)
                const float w = 0.5f - 0.5f * cospif((float)j * (1.0f / 256.0f));
                const float2 zz = Z[t][j >> 1];
                const float  v  = (j & 1) ? zz.y : zz.x;
                acc += w * v;
                env += w * w;
            }
        }
        out[(size_t)b * 600 + n] = acc / (256.0f * env);
    }
}

extern "C" void kernel_launch(void* const* d_in, const int* in_sizes, int n_in,
                              void* d_out, int out_size) {
    (void)in_sizes; (void)n_in; (void)out_size;
    const float* x = (const float*)d_in[0];
    float* out = (float*)d_out;
    istft_kernel<<<8192, NTHREADS>>>(x, out);
}